// round 11
// baseline (speedup 1.0000x reference)
#include <cuda_runtime.h>
#include <cuda_fp16.h>
#include <math.h>

#define N_ENT   64368
#define DIM     128
#define BATCH   512
#define SEQ     50
#define BN      64           // gemm n-tile width
#define NT2     1006         // ceil(64368/64)
#define NGRP2   76           // n-groups; grid = 4*76 = 304 (2 CTAs/SM)
#define NTP     80           // padded partial stride (one partial per CTA-group)
#define RSW     68           // words per smem row (272B)
#define ABYTES  (128 * 272)  // A tile bytes (34816)
#define BBYTES  (64 * 272)   // B tile bytes (17408)

// ---------------- scratch (device globals; no allocations allowed) ----------
__device__ float g_p1[16 * DIM];
__device__ float g_p2[16 * DIM];
__device__ float g_pe[SEQ * DIM];
__device__ float g_c;
__device__ __align__(16) __half g_uh[BATCH * DIM];
__device__ __align__(16) __half g_eh[N_ENT * DIM];     // fp16 entity_emb
__device__ __align__(16) float2 g_pms[BATCH * NTP];
__device__ float g_lp[BATCH];

// ---------------- helpers ----------------------------------------------------
__device__ __forceinline__ unsigned sptr(const void* p) {
    return (unsigned)__cvta_generic_to_shared(p);
}
__device__ __forceinline__ void cp_async16(unsigned dst, const void* src, int sz) {
    asm volatile("cp.async.cg.shared.global [%0], [%1], 16, %2;\n"
                 :: "r"(dst), "l"(src), "r"(sz));
}
__device__ __forceinline__ void cp_commit() { asm volatile("cp.async.commit_group;\n"); }
template <int N> __device__ __forceinline__ void cp_wait() {
    asm volatile("cp.async.wait_group %0;\n" :: "n"(N));
}
__device__ __forceinline__ void mma_f16(float* d, const unsigned* a, unsigned b0, unsigned b1) {
    asm volatile(
        "mma.sync.aligned.m16n8k16.row.col.f32.f16.f16.f32 "
        "{%0,%1,%2,%3}, {%4,%5,%6,%7}, {%8,%9}, {%0,%1,%2,%3};\n"
        : "+f"(d[0]), "+f"(d[1]), "+f"(d[2]), "+f"(d[3])
        : "r"(a[0]), "r"(a[1]), "r"(a[2]), "r"(a[3]), "r"(b0), "r"(b1));
}

// ---------------- K1: econv (0..4022) | W-partials (4023..4038) | PE (4039..4088)
__global__ void k1_kernel(const float* __restrict__ emb,
                          const float* __restrict__ W1, const float* __restrict__ W2,
                          const float* __restrict__ q,  const float* __restrict__ soft_bias) {
    const int bid = blockIdx.x;
    const int tid = threadIdx.x;

    if (bid < 4023) {
        size_t base = ((size_t)bid * 256 + tid) * 8;
        float4 a = *(const float4*)&emb[base];
        float4 b = *(const float4*)&emb[base + 4];
        __half2 h[4];
        h[0] = __floats2half2_rn(a.x, a.y);
        h[1] = __floats2half2_rn(a.z, a.w);
        h[2] = __floats2half2_rn(b.x, b.y);
        h[3] = __floats2half2_rn(b.z, b.w);
        *(uint4*)&g_eh[base] = *(uint4*)h;
    } else if (bid < 4039) {
        int p = bid - 4023;
        if (tid < 128) {
            float s1 = 0.f, s2 = 0.f;
            #pragma unroll
            for (int e = 0; e < 8; e++) {
                int er = p * 8 + e;
                float qe = q[er];
                s1 += qe * W1[er * DIM + tid];
                s2 += qe * W2[er * DIM + tid];
            }
            g_p1[p * DIM + tid] = s1;
            g_p2[p * DIM + tid] = s2;
        }
    } else {
        int l = bid - 4039;
        if (tid < 128) {
            float w = expf(-(float)(tid & ~1) * (logf(10000.0f) / (float)DIM));
            float arg = (float)l * w;
            g_pe[l * DIM + tid] = ((tid & 1) ? cosf(arg) : sinf(arg)) * 0.001f;
        }
        if (l == 0) {
            __shared__ float rq[128];
            if (tid < 128) rq[tid] = q[tid];
            __syncthreads();
            for (int o = 64; o; o >>= 1) {
                if (tid < o) rq[tid] += rq[tid + o];
                __syncthreads();
            }
            if (tid == 0) g_c = soft_bias[0] * rq[0];
        }
    }
}

// ---------------- K2: u_emb (2D block, PE table, inline r-reduction) ---------
__global__ void __launch_bounds__(1024)
uemb_kernel(const float* __restrict__ emb, const int* __restrict__ seeds) {
    int b  = blockIdx.x;
    int tx = threadIdx.x;              // dim 0..127
    int ty = threadIdx.y;              // 0..7
    int tid = ty * 128 + tx;
    int warp = tid >> 5, lane = tid & 31;

    __shared__ float v[SEQ][DIM];
    __shared__ float att[SEQ];
    __shared__ float sr1[DIM], sr2[DIM];
    __shared__ float dn;
    __shared__ float part[8][DIM];

    if (ty == 0) {
        float s = 0.f;
        #pragma unroll
        for (int p = 0; p < 16; p++) s += g_p1[p * DIM + tx];
        sr1[tx] = s;
    } else if (ty == 1) {
        float s = 0.f;
        #pragma unroll
        for (int p = 0; p < 16; p++) s += g_p2[p * DIM + tx];
        sr2[tx] = s;
    }

    for (int l = ty; l < SEQ; l += 8) {
        int idx = seeds[b * SEQ + l];
        v[l][tx] = emb[(size_t)idx * DIM + tx] + g_pe[l * DIM + tx];
    }
    __syncthreads();

    for (int l = warp; l < SEQ; l += 32) {
        float p = sr1[lane]      * v[l][lane]
                + sr1[lane + 32] * v[l][lane + 32]
                + sr1[lane + 64] * v[l][lane + 64]
                + sr1[lane + 96] * v[l][lane + 96];
        #pragma unroll
        for (int o = 16; o; o >>= 1) p += __shfl_xor_sync(0xffffffffu, p, o);
        if (lane == 0) att[l] = p;
    }
    if (warp == 0) {
        float p = sr2[lane]      * v[SEQ - 1][lane]
                + sr2[lane + 32] * v[SEQ - 1][lane + 32]
                + sr2[lane + 64] * v[SEQ - 1][lane + 64]
                + sr2[lane + 96] * v[SEQ - 1][lane + 96];
        #pragma unroll
        for (int o = 16; o; o >>= 1) p += __shfl_xor_sync(0xffffffffu, p, o);
        if (lane == 0) dn = p + g_c;
    }
    __syncthreads();
    if (tid < SEQ) att[tid] += dn;
    __syncthreads();

    float pacc = 0.f;
    for (int l = ty; l < SEQ; l += 8) pacc += att[l] * v[l][tx];
    part[ty][tx] = pacc;
    __syncthreads();
    if (ty < 4) part[ty][tx] += part[ty + 4][tx];
    __syncthreads();
    if (ty < 2) part[ty][tx] += part[ty + 2][tx];
    __syncthreads();
    if (ty == 0)
        g_uh[b * DIM + tx] = __float2half_rn(part[0][tx] + part[1][tx]);
}

// ---------------- K3: persistent fp16 GEMM + per-CTA accumulated LSE ---------
// grid = 304 (4 m-tiles x 76 n-groups), 256 threads, tile 128m x 64n.
// smem: A [34816] | B x 3 stages [3*17408] = 87040 B, 2 CTAs/SM.
extern __shared__ __align__(16) unsigned char dynraw[];

__global__ void __launch_bounds__(256, 2)
gemm_kernel(const float* __restrict__ out_bias, float* __restrict__ out) {
    __shared__ float sBias[BN];
    __shared__ float sRm[128][2];
    __shared__ float sRs[128][2];
    __shared__ float sAm[128];         // running row max (this CTA)
    __shared__ float sAs[128];         // running row sumexp

    const int tid  = threadIdx.x;
    const int warp = tid >> 5, lane = tid & 31;
    const int wm   = warp & 3;          // warp m index (4)
    const int wn   = warp >> 2;         // warp n index (2) -> 32-col halves
    const int m0   = (blockIdx.x & 3) * 128;
    const int grp  = blockIdx.x >> 2;   // 0..75

    const unsigned aBase = sptr(dynraw);
    unsigned bB[3];
    bB[0] = aBase + ABYTES;
    bB[1] = bB[0] + BBYTES;
    bB[2] = bB[1] + BBYTES;

    if (tid < 128) { sAm[tid] = -1e30f; sAs[tid] = 0.f; }

    // ---- load A tile once ---------------------------------------------------
    #pragma unroll
    for (int i = 0; i < 8; i++) {
        int lin = tid + i * 256;
        int r = lin >> 4, s = lin & 15;
        cp_async16(aBase + (unsigned)(r * 272 + s * 16),
                   &g_uh[(m0 + r) * DIM + s * 8], 16);
    }

    auto load_B = [&](int nt, unsigned bb) {
        #pragma unroll
        for (int i = 0; i < 4; i++) {
            int lin = tid + i * 256;
            int r = lin >> 4, s = lin & 15;   // r 0..63
            int g  = nt * BN + r;
            int gc = g < N_ENT ? g : 0;
            cp_async16(bb + (unsigned)(r * 272 + s * 16),
                       &g_eh[(size_t)gc * DIM + s * 8], g < N_ENT ? 16 : 0);
        }
    };

    // prologue: A + stage0 in group0; stage1 group1; stage2 group2
    load_B(grp, bB[0]);
    cp_commit();
    if (grp + NGRP2 < NT2) load_B(grp + NGRP2, bB[1]);
    cp_commit();
    if (grp + 2 * NGRP2 < NT2) load_B(grp + 2 * NGRP2, bB[2]);
    cp_commit();

    cp_wait<2>();                       // A + stage0 ready
    __syncthreads();

    // ---- hoist A fragments (32 m-rows per warp) into registers -------------
    unsigned aF[8][2][4];
    {
        const unsigned* sA = (const unsigned*)dynraw;
        const int ar = wm * 32 + (lane >> 2);
        #pragma unroll
        for (int ks = 0; ks < 8; ks++) {
            const int kp = ks * 8 + (lane & 3);
            #pragma unroll
            for (int mf = 0; mf < 2; mf++) {
                int r = ar + mf * 16;
                aF[ks][mf][0] = sA[r * RSW + kp];
                aF[ks][mf][1] = sA[(r + 8) * RSW + kp];
                aF[ks][mf][2] = sA[r * RSW + kp + 4];
                aF[ks][mf][3] = sA[(r + 8) * RSW + kp + 4];
            }
        }
    }

    int it = 0;
    for (int nt = grp; nt < NT2; nt += NGRP2, it++) {
        const int st = it % 3;

        if (it > 0) { cp_wait<2>(); __syncthreads(); }   // stage st ready

        if (tid < BN) {
            int g = nt * BN + tid;
            sBias[tid] = (g < N_ENT) ? out_bias[g] : 0.f;
        }

        // ---- mainloop: full K, no syncs ------------------------------------
        float acc[2][4][4];
        #pragma unroll
        for (int i = 0; i < 2; i++)
            #pragma unroll
            for (int j = 0; j < 4; j++)
                #pragma unroll
                for (int k = 0; k < 4; k++) acc[i][j][k] = 0.f;

        const unsigned* sB = (const unsigned*)(dynraw + (bB[st] - aBase));
        #pragma unroll
        for (int ks = 0; ks < 8; ks++) {
            const int kp = ks * 8 + (lane & 3);
            #pragma unroll
            for (int nf = 0; nf < 4; nf++) {
                int br = wn * 32 + nf * 8 + (lane >> 2);
                unsigned b0 = sB[br * RSW + kp];
                unsigned b1 = sB[br * RSW + kp + 4];
                mma_f16(acc[0][nf], aF[ks][0], b0, b1);
                mma_f16(acc[1][nf], aF[ks][1], b0, b1);
            }
        }
        __syncthreads();                 // stage st consumed; sBias visible

        // refill stage st with tile nt + 3*NGRP2
        if (nt + 3 * NGRP2 < NT2) load_B(nt + 3 * NGRP2, bB[st]);
        cp_commit();                     // keep group counting uniform

        // ---- epilogue: bias, store, streaming (max, sumexp) ----------------
        const float NEG = -1e30f;
        #pragma unroll
        for (int mf = 0; mf < 2; mf++) {
            #pragma unroll
            for (int h = 0; h < 2; h++) {
                const int rl = wm * 32 + mf * 16 + h * 8 + (lane >> 2);
                const size_t grow = (size_t)(m0 + rl) * N_ENT;
                float mx = NEG;
                #pragma unroll
                for (int nf = 0; nf < 4; nf++) {
                    int c = wn * 32 + nf * 8 + ((lane & 3) << 1);
                    int g = nt * BN + c;
                    float v0 = acc[mf][nf][2 * h]     + sBias[c];
                    float v1 = acc[mf][nf][2 * h + 1] + sBias[c + 1];
                    if (g + 1 < N_ENT) {
                        *(float2*)&out[grow + g] = make_float2(v0, v1);
                    } else if (g < N_ENT) {
                        out[grow + g] = v0;
                        v1 = NEG;
                    } else {
                        v0 = NEG; v1 = NEG;
                    }
                    acc[mf][nf][2 * h]     = v0;
                    acc[mf][nf][2 * h + 1] = v1;
                    mx = fmaxf(mx, fmaxf(v0, v1));
                }
                float s = 0.f;
                #pragma unroll
                for (int nf = 0; nf < 4; nf++)
                    s += __expf(acc[mf][nf][2 * h] - mx)
                       + __expf(acc[mf][nf][2 * h + 1] - mx);
                #pragma unroll
                for (int off = 1; off <= 2; off <<= 1) {
                    float om = __shfl_xor_sync(0xffffffffu, mx, off);
                    float os = __shfl_xor_sync(0xffffffffu, s,  off);
                    float nm = fmaxf(mx, om);
                    s = s * __expf(mx - nm) + os * __expf(om - nm);
                    mx = nm;
                }
                if ((lane & 3) == 0) {
                    sRm[rl][wn] = mx;
                    sRs[rl][wn] = s;
                }
            }
        }
        __syncthreads();
        if (tid < 128) {                 // merge tile partial into running acc
            float ma = sRm[tid][0], mb = sRm[tid][1];
            float sa = sRs[tid][0], sb = sRs[tid][1];
            float nm = fmaxf(ma, mb);
            float ss = sa * __expf(ma - nm) + sb * __expf(mb - nm);
            float am = sAm[tid];
            float nm2 = fmaxf(am, nm);
            sAs[tid] = sAs[tid] * __expf(am - nm2) + ss * __expf(nm - nm2);
            sAm[tid] = nm2;
        }
        __syncthreads();                 // protect sRm/sRs reuse
    }

    if (tid < 128)
        g_pms[(m0 + tid) * NTP + grp] = make_float2(sAm[tid], sAs[tid]);
}

// ---------------- K4: per-row logsumexp + picked (76 partials/row) -----------
__global__ void lse_kernel(const float* __restrict__ out,
                           const int* __restrict__ labels) {
    int w = threadIdx.x >> 5, lane = threadIdx.x & 31;
    int b = blockIdx.x * 8 + w;        // grid 64 x 256 -> 512 rows
    float mx0 = -1e30f, mx1 = -1e30f, mx2 = -1e30f;
    float s0 = 0.f, s1 = 0.f, s2 = 0.f;
    {
        float2 p = g_pms[b * NTP + lane];
        mx0 = p.x; s0 = p.y;
    }
    {
        float2 p = g_pms[b * NTP + lane + 32];
        mx1 = p.x; s1 = p.y;
    }
    if (lane + 64 < NGRP2) {
        float2 p = g_pms[b * NTP + lane + 64];
        mx2 = p.x; s2 = p.y;
    }
    float nm01 = fmaxf(mx0, mx1);
    float s01  = s0 * __expf(mx0 - nm01) + s1 * __expf(mx1 - nm01);
    float mx   = fmaxf(nm01, mx2);
    float s    = s01 * __expf(nm01 - mx) + s2 * __expf(mx2 - mx);
    #pragma unroll
    for (int o = 16; o; o >>= 1) {
        float om = __shfl_xor_sync(0xffffffffu, mx, o);
        float os = __shfl_xor_sync(0xffffffffu, s,  o);
        float nm = fmaxf(mx, om);
        s = s * __expf(mx - nm) + os * __expf(om - nm);
        mx = nm;
    }
    if (lane == 0) {
        float logz = mx + logf(s);
        g_lp[b] = logz - out[(size_t)b * N_ENT + labels[b]];
    }
}

// ---------------- K5: mean loss -> tail of d_out ------------------------------
__global__ void loss_kernel(float* __restrict__ out, int out_size) {
    int tid = threadIdx.x;             // 512
    __shared__ float red[BATCH];
    red[tid] = g_lp[tid];
    __syncthreads();
    for (int o = 256; o; o >>= 1) {
        if (tid < o) red[tid] += red[tid + o];
        __syncthreads();
    }
    __shared__ float loss_s;
    if (tid == 0) loss_s = red[0] / (float)BATCH;
    __syncthreads();
    const long base = (long)BATCH * N_ENT;
    for (long i = base + tid; i < (long)out_size; i += 512)
        out[i] = loss_s;
}

// ---------------- launch ------------------------------------------------------
extern "C" void kernel_launch(void* const* d_in, const int* in_sizes, int n_in,
                              void* d_out, int out_size) {
    const float* entity_emb = (const float*)d_in[0];
    const float* W1         = (const float*)d_in[1];
    const float* W2         = (const float*)d_in[2];
    const float* q          = (const float*)d_in[3];
    const float* soft_bias  = (const float*)d_in[4];
    const float* out_bias   = (const float*)d_in[5];
    const int*   seed_sets  = (const int*)d_in[6];   // jax default: int64 -> int32
    const int*   labels     = (const int*)d_in[7];
    float* out = (float*)d_out;

    const int dyn_bytes = ABYTES + 3 * BBYTES;       // 87,040 B
    cudaFuncSetAttribute(gemm_kernel,
                         cudaFuncAttributeMaxDynamicSharedMemorySize, dyn_bytes);

    k1_kernel<<<4089, 256>>>(entity_emb, W1, W2, q, soft_bias);
    uemb_kernel<<<BATCH, dim3(128, 8)>>>(entity_emb, seed_sets);
    gemm_kernel<<<4 * NGRP2, 256, dyn_bytes>>>(out_bias, out);
    lse_kernel<<<64, 256>>>(out, labels);
    loss_kernel<<<1, BATCH>>>(out, out_size);
}